// round 6
// baseline (speedup 1.0000x reference)
#include <cuda_runtime.h>
#include <cuda_bf16.h>
#include <cstdint>

// Problem constants: B=4, H=16, S=2048, D=64
#define S_LEN 2048
#define DH    64
#define BHN   64
#define BQ    128
#define BKT   128
#define NTILE 16

// smem: QH,QL + double-buffered KH/KL/VH/VL, all [128x64] bf16 swizzled tiles
#define OFF_QH 0
#define OFF_QL 16384
#define OFF_KV 32768            // + buf*65536 : KH, KL(+16K), VH(+32K), VL(+48K)
#define SMEM_SZ 163840

typedef unsigned long long ull;

// ---------------- helpers ----------------
__device__ __forceinline__ uint32_t s2u(const void* p) {
    uint32_t a;
    asm("{ .reg .u64 t; cvta.to.shared.u64 t, %1; cvt.u32.u64 %0, t; }" : "=r"(a) : "l"(p));
    return a;
}
__device__ __forceinline__ void ldsm4(uint32_t a, uint32_t* r) {
    asm volatile("ldmatrix.sync.aligned.m8n8.x4.shared.b16 {%0,%1,%2,%3}, [%4];"
                 : "=r"(r[0]), "=r"(r[1]), "=r"(r[2]), "=r"(r[3]) : "r"(a));
}
__device__ __forceinline__ void ldsm4t(uint32_t a, uint32_t* r) {
    asm volatile("ldmatrix.sync.aligned.m8n8.x4.trans.shared.b16 {%0,%1,%2,%3}, [%4];"
                 : "=r"(r[0]), "=r"(r[1]), "=r"(r[2]), "=r"(r[3]) : "r"(a));
}
__device__ __forceinline__ void mma_bf16(float* d, const uint32_t* a,
                                         uint32_t b0, uint32_t b1) {
    asm volatile("mma.sync.aligned.m16n8k16.row.col.f32.bf16.bf16.f32 "
                 "{%0,%1,%2,%3},{%4,%5,%6,%7},{%8,%9},{%0,%1,%2,%3};"
                 : "+f"(d[0]), "+f"(d[1]), "+f"(d[2]), "+f"(d[3])
                 : "r"(a[0]), "r"(a[1]), "r"(a[2]), "r"(a[3]), "r"(b0), "r"(b1));
}
__device__ __forceinline__ uint32_t pk2(float lo, float hi) {
    uint32_t r;
    asm("cvt.rn.bf16x2.f32 %0, %1, %2;" : "=r"(r) : "f"(hi), "f"(lo));
    return r;
}
__device__ __forceinline__ float lo16f(uint32_t u) { return __uint_as_float(u << 16); }
__device__ __forceinline__ float hi16f(uint32_t u) { return __uint_as_float(u & 0xFFFF0000u); }

// issue 8 float4 loads for one [128x64] fp32 tile
__device__ __forceinline__ void ldg8(const float* __restrict__ g, float4* r, int tid) {
    const float4* g4 = (const float4*)g;
    #pragma unroll
    for (int it = 0; it < 8; ++it) r[it] = g4[tid + it * 256];
}
// convert 8 float4 to bf16 hi/lo, store swizzled (128B rows)
__device__ __forceinline__ void cvtst8(const float4* r, char* smp,
                                       uint32_t hoff, uint32_t loff, int tid) {
    #pragma unroll
    for (int it = 0; it < 8; ++it) {
        int i = tid + it * 256;
        float4 t = r[it];
        int row = i >> 4, d0 = (i & 15) << 2;
        uint32_t off = (uint32_t)row * 128 +
                       (((uint32_t)(d0 << 1)) ^ (((uint32_t)row & 7) << 4));
        uint32_t h01 = pk2(t.x, t.y), h23 = pk2(t.z, t.w);
        uint32_t l01 = pk2(t.x - lo16f(h01), t.y - hi16f(h01));
        uint32_t l23 = pk2(t.z - lo16f(h23), t.w - hi16f(h23));
        *(ull*)(smp + hoff + off) = (ull)h01 | ((ull)h23 << 32);
        *(ull*)(smp + loff + off) = (ull)l01 | ((ull)l23 << 32);
    }
}

__global__ __launch_bounds__(256, 1)
void attn_mma(const float* __restrict__ q, const float* __restrict__ k,
              const float* __restrict__ v, const int* __restrict__ mask,
              float* __restrict__ out, float* __restrict__ p)
{
    extern __shared__ char sm[];
    const uint32_t sb = s2u(sm);
    const int tid = threadIdx.x;
    const int wid = tid >> 5, lane = tid & 31;
    const int bh = blockIdx.y;
    const int q0 = blockIdx.x * BQ;
    const int mr = wid * 16;

    const float* kbase = k + (size_t)bh * S_LEN * DH;
    const float* vbase = v + (size_t)bh * S_LEN * DH;

    // ---- prologue: Q tile + first K/V tiles
    {
        float4 r[8];
        ldg8(q + ((size_t)bh * S_LEN + q0) * DH, r, tid);
        cvtst8(r, sm, OFF_QH, OFF_QL, tid);
        ldg8(kbase, r, tid);
        cvtst8(r, sm, OFF_KV, OFF_KV + 16384, tid);
        ldg8(vbase, r, tid);
        cvtst8(r, sm, OFF_KV + 32768, OFF_KV + 49152, tid);
    }
    __syncthreads();

    float Oacc[8][4];
    #pragma unroll
    for (int i = 0; i < 8; ++i)
        #pragma unroll
        for (int c = 0; c < 4; ++c) Oacc[i][c] = 0.f;
    float esum0 = 0.f, esum1 = 0.f;

    // epilogue thread mapping (m16n8 accum layout)
    const int r0l = mr + (lane >> 2);
    const int coff = (lane & 3) * 2;

    // ldmatrix lane->row/col mapping (XOR applied AFTER column adds)
    const int arow = mr + (lane & 15);
    const uint32_t arowoff = (uint32_t)arow * 128;
    const uint32_t acol0 = ((uint32_t)(lane >> 4)) << 4;
    const uint32_t axor = ((uint32_t)arow & 7) << 4;
    const int nrow = ((lane >> 4) << 3) + (lane & 7);
    const uint32_t nrowoff = (uint32_t)nrow * 128;
    const uint32_t ncol0 = (((uint32_t)lane >> 3) & 1) << 4;
    const uint32_t nxor = ((uint32_t)nrow & 7) << 4;
    const int vrow = (((lane >> 3) & 1) << 3) + (lane & 7);
    const uint32_t vrowoff = (uint32_t)vrow * 128;
    const uint32_t vcol0 = ((uint32_t)(lane >> 4)) << 4;
    const uint32_t vxor = ((uint32_t)vrow & 7) << 4;

    for (int kb = 0; kb < NTILE; ++kb) {
        const uint32_t cvb = OFF_KV + (uint32_t)(kb & 1) * 65536;   // current buf
        const uint32_t nxb = OFF_KV + (uint32_t)((kb & 1) ^ 1) * 65536;
        const bool more = (kb < NTILE - 1);

        float4 ldreg[8];
        if (more) ldg8(kbase + (size_t)(kb + 1) * BKT * DH, ldreg, tid);

        // ---- GEMM1: S[16 x 128] per warp = Q . K^T (3-term bf16 split)
        float acc[16][4];
        #pragma unroll
        for (int i = 0; i < 16; ++i)
            #pragma unroll
            for (int c = 0; c < 4; ++c) acc[i][c] = 0.f;

        #pragma unroll
        for (int ks = 0; ks < 4; ++ks) {
            uint32_t ah[4], al[4];
            const uint32_t ao = arowoff + ((acol0 + (uint32_t)ks * 32) ^ axor);
            ldsm4(sb + OFF_QH + ao, ah);
            ldsm4(sb + OFF_QL + ao, al);
            #pragma unroll
            for (int np = 0; np < 8; ++np) {
                uint32_t bh4[4], bl4[4];
                const uint32_t bo = nrowoff + (uint32_t)np * 2048 +
                                    ((ncol0 + (uint32_t)ks * 32) ^ nxor);
                ldsm4(sb + cvb + bo, bh4);
                ldsm4(sb + cvb + 16384 + bo, bl4);
                mma_bf16(acc[np * 2], ah, bh4[0], bh4[1]);
                mma_bf16(acc[np * 2], ah, bl4[0], bl4[1]);
                mma_bf16(acc[np * 2], al, bh4[0], bh4[1]);
                mma_bf16(acc[np * 2 + 1], ah, bh4[2], bh4[3]);
                mma_bf16(acc[np * 2 + 1], ah, bl4[2], bl4[3]);
                mma_bf16(acc[np * 2 + 1], al, bh4[2], bh4[3]);
            }
        }

        // next-K convert to other buffer; issue next-V loads
        if (more) {
            cvtst8(ldreg, sm, nxb, nxb + 16384, tid);
            ldg8(vbase + (size_t)(kb + 1) * BKT * DH, ldreg, tid);
        }

        // ---- epilogue: mask + __expf, p write, pack E frags in registers
        uint32_t Eh[8][4], El[8][4];
        const int* mrow0 = mask + (size_t)(q0 + r0l) * S_LEN + kb * BKT + coff;
        const int* mrow1 = mrow0 + 8 * S_LEN;
        float* prow0 = p + ((size_t)(bh * S_LEN) + q0 + r0l) * S_LEN + kb * BKT + coff;
        float* prow1 = prow0 + (size_t)8 * S_LEN;
        #pragma unroll
        for (int nt = 0; nt < 16; ++nt) {
            const int2 m0 = *(const int2*)(mrow0 + nt * 8);
            const int2 m1 = *(const int2*)(mrow1 + nt * 8);
            float e0 = m0.x ? __expf(acc[nt][0] * 0.125f) : 0.f;
            float e1 = m0.y ? __expf(acc[nt][1] * 0.125f) : 0.f;
            float e2 = m1.x ? __expf(acc[nt][2] * 0.125f) : 0.f;
            float e3 = m1.y ? __expf(acc[nt][3] * 0.125f) : 0.f;
            *(float2*)(prow0 + nt * 8) = make_float2(e0, e1);
            *(float2*)(prow1 + nt * 8) = make_float2(e2, e3);
            esum0 += e0 + e1;
            esum1 += e2 + e3;
            uint32_t u01 = pk2(e0, e1), u23 = pk2(e2, e3);
            const int kk = nt >> 1, sl = (nt & 1) * 2;
            Eh[kk][sl + 0] = u01;
            Eh[kk][sl + 1] = u23;
            El[kk][sl + 0] = pk2(e0 - lo16f(u01), e1 - hi16f(u01));
            El[kk][sl + 1] = pk2(e2 - lo16f(u23), e3 - hi16f(u23));
        }

        // next-V convert (loads covered by epilogue above)
        if (more) cvtst8(ldreg, sm, nxb + 32768, nxb + 49152, tid);

        // ---- GEMM2: O[16 x 64] += E . V (V via ldmatrix.trans, 3-term split)
        #pragma unroll
        for (int kk = 0; kk < 8; ++kk) {
            const uint32_t vrt = vrowoff + (uint32_t)kk * 2048;
            #pragma unroll
            for (int dt2 = 0; dt2 < 4; ++dt2) {
                uint32_t vh4[4], vl4[4];
                const uint32_t o = vrt + ((vcol0 + (uint32_t)dt2 * 32) ^ vxor);
                ldsm4t(sb + cvb + 32768 + o, vh4);
                ldsm4t(sb + cvb + 49152 + o, vl4);
                mma_bf16(Oacc[dt2 * 2], Eh[kk], vh4[0], vh4[1]);
                mma_bf16(Oacc[dt2 * 2], Eh[kk], vl4[0], vl4[1]);
                mma_bf16(Oacc[dt2 * 2], El[kk], vh4[0], vh4[1]);
                mma_bf16(Oacc[dt2 * 2 + 1], Eh[kk], vh4[2], vh4[3]);
                mma_bf16(Oacc[dt2 * 2 + 1], Eh[kk], vl4[2], vl4[3]);
                mma_bf16(Oacc[dt2 * 2 + 1], El[kk], vh4[2], vh4[3]);
            }
        }
        __syncthreads();    // all reads of cur done; nxt fully written
    }

    // ---- row sums (quad reduce), normalized out
    esum0 += __shfl_xor_sync(0xffffffffu, esum0, 1);
    esum0 += __shfl_xor_sync(0xffffffffu, esum0, 2);
    esum1 += __shfl_xor_sync(0xffffffffu, esum1, 1);
    esum1 += __shfl_xor_sync(0xffffffffu, esum1, 2);
    const float inv0 = 1.f / esum0, inv1 = 1.f / esum1;
    float* orow0 = out + ((size_t)(bh * S_LEN) + q0 + r0l) * DH + coff;
    float* orow1 = orow0 + 8 * DH;
    #pragma unroll
    for (int dt = 0; dt < 8; ++dt) {
        *(float2*)(orow0 + dt * 8) = make_float2(Oacc[dt][0] * inv0, Oacc[dt][1] * inv0);
        *(float2*)(orow1 + dt * 8) = make_float2(Oacc[dt][2] * inv1, Oacc[dt][3] * inv1);
    }

    // ---- fused p normalization for this CTA's 128 rows (no global sync needed)
    float* inv_sm = (float*)sm;            // reuse tile smem
    __syncthreads();                       // smem reads done
    if ((lane & 3) == 0) {
        inv_sm[r0l] = inv0;
        inv_sm[r0l + 8] = inv1;
    }
    __syncthreads();
    float4* p4 = (float4*)(p + ((size_t)(bh * S_LEN) + q0) * S_LEN);
    #pragma unroll 4
    for (int i = tid; i < BQ * S_LEN / 4; i += 256) {
        float inv = inv_sm[i >> 9];        // 512 float4 per row
        float4 t = p4[i];
        t.x *= inv; t.y *= inv; t.z *= inv; t.w *= inv;
        p4[i] = t;
    }
}

extern "C" void kernel_launch(void* const* d_in, const int* in_sizes, int n_in,
                              void* d_out, int out_size)
{
    const float* q    = (const float*)d_in[0];
    const float* k    = (const float*)d_in[1];
    const float* v    = (const float*)d_in[2];
    const int*   mask = (const int*)d_in[3];

    float* out = (float*)d_out;
    float* p   = out + (size_t)BHN * S_LEN * DH;

    cudaFuncSetAttribute(attn_mma, cudaFuncAttributeMaxDynamicSharedMemorySize, SMEM_SZ);
    dim3 g1(S_LEN / BQ, BHN);
    attn_mma<<<g1, 256, SMEM_SZ>>>(q, k, v, mask, out, p);
}

// round 7
// speedup vs baseline: 1.2385x; 1.2385x over previous
#include <cuda_runtime.h>
#include <cuda_bf16.h>
#include <cstdint>

// Problem constants: B=4, H=16, S=2048, D=64
#define S_LEN 2048
#define DH    64
#define BHN   64
#define BQ    64            // query rows per CTA
#define BKT   128           // key rows per tile
#define NTILE 16

// smem: Q [64x64], K/V [128x64] bf16 swizzled tiles (single-buffered)
#define OFF_QH 0
#define OFF_QL 8192
#define OFF_KH 16384
#define OFF_KL 32768
#define OFF_VH 49152
#define OFF_VL 65536
#define SMEM_SZ 81920
// post-loop reuse
#define OFF_RS  OFF_QH          // float rsum[2][64]
#define OFF_INV (OFF_QH + 512)  // float inv_s[64]
#define OFF_OSM OFF_KH          // float Osm[64][64]

typedef unsigned long long ull;

// ---------------- helpers ----------------
__device__ __forceinline__ uint32_t s2u(const void* p) {
    uint32_t a;
    asm("{ .reg .u64 t; cvta.to.shared.u64 t, %1; cvt.u32.u64 %0, t; }" : "=r"(a) : "l"(p));
    return a;
}
__device__ __forceinline__ void ldsm4(uint32_t a, uint32_t* r) {
    asm volatile("ldmatrix.sync.aligned.m8n8.x4.shared.b16 {%0,%1,%2,%3}, [%4];"
                 : "=r"(r[0]), "=r"(r[1]), "=r"(r[2]), "=r"(r[3]) : "r"(a));
}
__device__ __forceinline__ void ldsm4t(uint32_t a, uint32_t* r) {
    asm volatile("ldmatrix.sync.aligned.m8n8.x4.trans.shared.b16 {%0,%1,%2,%3}, [%4];"
                 : "=r"(r[0]), "=r"(r[1]), "=r"(r[2]), "=r"(r[3]) : "r"(a));
}
__device__ __forceinline__ void mma_bf16(float* d, const uint32_t* a,
                                         uint32_t b0, uint32_t b1) {
    asm volatile("mma.sync.aligned.m16n8k16.row.col.f32.bf16.bf16.f32 "
                 "{%0,%1,%2,%3},{%4,%5,%6,%7},{%8,%9},{%0,%1,%2,%3};"
                 : "+f"(d[0]), "+f"(d[1]), "+f"(d[2]), "+f"(d[3])
                 : "r"(a[0]), "r"(a[1]), "r"(a[2]), "r"(a[3]), "r"(b0), "r"(b1));
}
__device__ __forceinline__ uint32_t pk2(float lo, float hi) {
    uint32_t r;
    asm("cvt.rn.bf16x2.f32 %0, %1, %2;" : "=r"(r) : "f"(hi), "f"(lo));
    return r;
}
__device__ __forceinline__ float lo16f(uint32_t u) { return __uint_as_float(u << 16); }
__device__ __forceinline__ float hi16f(uint32_t u) { return __uint_as_float(u & 0xFFFF0000u); }

// load+convert one [ROWS x 64] fp32 tile -> bf16 hi/lo swizzled (128B rows)
template<int ITERS>
__device__ __forceinline__ void ldcvt(const float* __restrict__ g, char* smp,
                                      uint32_t hoff, uint32_t loff, int tid) {
    const float4* g4 = (const float4*)g;
    #pragma unroll
    for (int it = 0; it < ITERS; ++it) {
        int i = tid + it * 256;
        float4 t = g4[i];
        int row = i >> 4, d0 = (i & 15) << 2;
        uint32_t off = (uint32_t)row * 128 +
                       (((uint32_t)(d0 << 1)) ^ (((uint32_t)row & 7) << 4));
        uint32_t h01 = pk2(t.x, t.y), h23 = pk2(t.z, t.w);
        uint32_t l01 = pk2(t.x - lo16f(h01), t.y - hi16f(h01));
        uint32_t l23 = pk2(t.z - lo16f(h23), t.w - hi16f(h23));
        *(ull*)(smp + hoff + off) = (ull)h01 | ((ull)h23 << 32);
        *(ull*)(smp + loff + off) = (ull)l01 | ((ull)l23 << 32);
    }
}

__global__ __launch_bounds__(256, 2)
void attn_mma(const float* __restrict__ q, const float* __restrict__ k,
              const float* __restrict__ v, const int* __restrict__ mask,
              float* __restrict__ out, float* __restrict__ p)
{
    extern __shared__ char sm[];
    const uint32_t sb = s2u(sm);
    const int tid = threadIdx.x;
    const int wid = tid >> 5, lane = tid & 31;
    const int rg = wid >> 1;                 // row group (16 rows each)
    const int nhalf = wid & 1;               // s-column half (0..63 / 64..127)
    const int bh = blockIdx.y;
    const int q0 = blockIdx.x * BQ;

    const float* kbase = k + (size_t)bh * S_LEN * DH;
    const float* vbase = v + (size_t)bh * S_LEN * DH;

    // Q tile once [64 x 64]
    ldcvt<4>(q + ((size_t)bh * S_LEN + q0) * DH, sm, OFF_QH, OFF_QL, tid);

    float Oacc[8][4];
    #pragma unroll
    for (int i = 0; i < 8; ++i)
        #pragma unroll
        for (int c = 0; c < 4; ++c) Oacc[i][c] = 0.f;
    float esum0 = 0.f, esum1 = 0.f;

    // epilogue thread mapping (m16n8 accum layout)
    const int r0l = rg * 16 + (lane >> 2);   // local row (and +8)
    const int coff = (lane & 3) * 2;

    // ldmatrix lane mappings (XOR applied AFTER column adds)
    const int arow = rg * 16 + (lane & 15);
    const uint32_t arowoff = (uint32_t)arow * 128;
    const uint32_t acol0 = ((uint32_t)(lane >> 4)) << 4;
    const uint32_t axor = ((uint32_t)arow & 7) << 4;
    const int nrow = ((lane >> 4) << 3) + (lane & 7);
    const uint32_t nbase = (uint32_t)(nhalf * 64 + nrow) * 128;   // k-row half offset
    const uint32_t ncol0 = (((uint32_t)lane >> 3) & 1) << 4;
    const uint32_t nxor = ((uint32_t)(nrow & 7)) << 4;
    const int vrow = (((lane >> 3) & 1) << 3) + (lane & 7);
    const uint32_t vbase_off = (uint32_t)(nhalf * 64 + vrow) * 128;
    const uint32_t vcol0 = ((uint32_t)(lane >> 4)) << 4;
    const uint32_t vxor = ((uint32_t)(vrow & 7)) << 4;

    for (int kb = 0; kb < NTILE; ++kb) {
        __syncthreads();                     // prev tile reads done
        ldcvt<8>(kbase + (size_t)kb * BKT * DH, sm, OFF_KH, OFF_KL, tid);
        ldcvt<8>(vbase + (size_t)kb * BKT * DH, sm, OFF_VH, OFF_VL, tid);
        __syncthreads();

        // ---- GEMM1: S[16 x 64] per warp = Q . K^T (3-term bf16 split)
        float acc[8][4];
        #pragma unroll
        for (int i = 0; i < 8; ++i)
            #pragma unroll
            for (int c = 0; c < 4; ++c) acc[i][c] = 0.f;

        #pragma unroll
        for (int ks = 0; ks < 4; ++ks) {
            uint32_t ah[4], al[4];
            const uint32_t ao = arowoff + ((acol0 + (uint32_t)ks * 32) ^ axor);
            ldsm4(sb + OFF_QH + ao, ah);
            ldsm4(sb + OFF_QL + ao, al);
            #pragma unroll
            for (int np = 0; np < 4; ++np) {
                uint32_t bh4[4], bl4[4];
                const uint32_t bo = nbase + (uint32_t)np * 2048 +
                                    ((ncol0 + (uint32_t)ks * 32) ^ nxor);
                ldsm4(sb + OFF_KH + bo, bh4);
                ldsm4(sb + OFF_KL + bo, bl4);
                mma_bf16(acc[np * 2], ah, bh4[0], bh4[1]);
                mma_bf16(acc[np * 2], ah, bl4[0], bl4[1]);
                mma_bf16(acc[np * 2], al, bh4[0], bh4[1]);
                mma_bf16(acc[np * 2 + 1], ah, bh4[2], bh4[3]);
                mma_bf16(acc[np * 2 + 1], ah, bl4[2], bl4[3]);
                mma_bf16(acc[np * 2 + 1], al, bh4[2], bh4[3]);
            }
        }

        // ---- epilogue: mask + __expf, unnormalized p write, E frags in regs
        uint32_t Eh[4][4], El[4][4];
        const int cb = kb * BKT + nhalf * 64 + coff;
        const int* mrow0 = mask + (size_t)(q0 + r0l) * S_LEN + cb;
        const int* mrow1 = mrow0 + 8 * S_LEN;
        float* prow0 = p + ((size_t)(bh * S_LEN) + q0 + r0l) * S_LEN + cb;
        float* prow1 = prow0 + (size_t)8 * S_LEN;
        #pragma unroll
        for (int nt = 0; nt < 8; ++nt) {
            const int2 m0 = *(const int2*)(mrow0 + nt * 8);
            const int2 m1 = *(const int2*)(mrow1 + nt * 8);
            float e0 = m0.x ? __expf(acc[nt][0] * 0.125f) : 0.f;
            float e1 = m0.y ? __expf(acc[nt][1] * 0.125f) : 0.f;
            float e2 = m1.x ? __expf(acc[nt][2] * 0.125f) : 0.f;
            float e3 = m1.y ? __expf(acc[nt][3] * 0.125f) : 0.f;
            *(float2*)(prow0 + nt * 8) = make_float2(e0, e1);
            *(float2*)(prow1 + nt * 8) = make_float2(e2, e3);
            esum0 += e0 + e1;
            esum1 += e2 + e3;
            uint32_t u01 = pk2(e0, e1), u23 = pk2(e2, e3);
            const int kk = nt >> 1, sl = (nt & 1) * 2;
            Eh[kk][sl + 0] = u01;
            Eh[kk][sl + 1] = u23;
            El[kk][sl + 0] = pk2(e0 - lo16f(u01), e1 - hi16f(u01));
            El[kk][sl + 1] = pk2(e2 - lo16f(u23), e3 - hi16f(u23));
        }

        // ---- GEMM2: O[16 x 64] += E(k-half) . V(k-half)  (3-term split)
        #pragma unroll
        for (int kk = 0; kk < 4; ++kk) {
            const uint32_t vrt = vbase_off + (uint32_t)kk * 2048;
            #pragma unroll
            for (int dt2 = 0; dt2 < 4; ++dt2) {
                uint32_t vh4[4], vl4[4];
                const uint32_t o = vrt + ((vcol0 + (uint32_t)dt2 * 32) ^ vxor);
                ldsm4t(sb + OFF_VH + o, vh4);
                ldsm4t(sb + OFF_VL + o, vl4);
                mma_bf16(Oacc[dt2 * 2], Eh[kk], vh4[0], vh4[1]);
                mma_bf16(Oacc[dt2 * 2], Eh[kk], vl4[0], vl4[1]);
                mma_bf16(Oacc[dt2 * 2], El[kk], vh4[0], vh4[1]);
                mma_bf16(Oacc[dt2 * 2 + 1], Eh[kk], vh4[2], vh4[3]);
                mma_bf16(Oacc[dt2 * 2 + 1], Eh[kk], vl4[2], vl4[3]);
                mma_bf16(Oacc[dt2 * 2 + 1], El[kk], vh4[2], vh4[3]);
            }
        }
    }
    __syncthreads();      // all tile reads done; smem reusable

    // ---- row sums: quad reduce, publish per-half, combine
    esum0 += __shfl_xor_sync(0xffffffffu, esum0, 1);
    esum0 += __shfl_xor_sync(0xffffffffu, esum0, 2);
    esum1 += __shfl_xor_sync(0xffffffffu, esum1, 1);
    esum1 += __shfl_xor_sync(0xffffffffu, esum1, 2);
    float* rsum = (float*)(sm + OFF_RS);
    float* inv_s = (float*)(sm + OFF_INV);
    if ((lane & 3) == 0) {
        rsum[nhalf * 64 + r0l] = esum0;
        rsum[nhalf * 64 + r0l + 8] = esum1;
    }
    // ---- O combine: nhalf=1 warps deposit partial O
    float* Osm = (float*)(sm + OFF_OSM);
    if (nhalf == 1) {
        #pragma unroll
        for (int dt = 0; dt < 8; ++dt) {
            *(float2*)&Osm[r0l * 64 + dt * 8 + coff] = make_float2(Oacc[dt][0], Oacc[dt][1]);
            *(float2*)&Osm[(r0l + 8) * 64 + dt * 8 + coff] = make_float2(Oacc[dt][2], Oacc[dt][3]);
        }
    }
    __syncthreads();
    if (tid < 64) inv_s[tid] = 1.f / (rsum[tid] + rsum[64 + tid]);
    __syncthreads();

    if (nhalf == 0) {
        const float inv0 = inv_s[r0l], inv1 = inv_s[r0l + 8];
        float* orow0 = out + ((size_t)(bh * S_LEN) + q0 + r0l) * DH + coff;
        float* orow1 = orow0 + 8 * DH;
        #pragma unroll
        for (int dt = 0; dt < 8; ++dt) {
            float2 a0 = *(float2*)&Osm[r0l * 64 + dt * 8 + coff];
            float2 a1 = *(float2*)&Osm[(r0l + 8) * 64 + dt * 8 + coff];
            *(float2*)(orow0 + dt * 8) =
                make_float2((Oacc[dt][0] + a0.x) * inv0, (Oacc[dt][1] + a0.y) * inv0);
            *(float2*)(orow1 + dt * 8) =
                make_float2((Oacc[dt][2] + a1.x) * inv1, (Oacc[dt][3] + a1.y) * inv1);
        }
    }

    // ---- fused p normalization for this CTA's 64 rows
    float4* p4 = (float4*)(p + ((size_t)(bh * S_LEN) + q0) * S_LEN);
    #pragma unroll 4
    for (int i = tid; i < BQ * S_LEN / 4; i += 256) {
        float inv = inv_s[i >> 9];           // 512 float4 per row
        float4 t = p4[i];
        t.x *= inv; t.y *= inv; t.z *= inv; t.w *= inv;
        p4[i] = t;
    }
}

extern "C" void kernel_launch(void* const* d_in, const int* in_sizes, int n_in,
                              void* d_out, int out_size)
{
    const float* q    = (const float*)d_in[0];
    const float* k    = (const float*)d_in[1];
    const float* v    = (const float*)d_in[2];
    const int*   mask = (const int*)d_in[3];

    float* out = (float*)d_out;
    float* p   = out + (size_t)BHN * S_LEN * DH;

    cudaFuncSetAttribute(attn_mma, cudaFuncAttributeMaxDynamicSharedMemorySize, SMEM_SZ);
    dim3 g1(S_LEN / BQ, BHN);
    attn_mma<<<g1, 256, SMEM_SZ>>>(q, k, v, mask, out, p);
}

// round 8
// speedup vs baseline: 1.2672x; 1.0231x over previous
#include <cuda_runtime.h>
#include <cuda_bf16.h>
#include <cstdint>

// Problem constants: B=4, H=16, S=2048, D=64
#define S_LEN 2048
#define DH    64
#define BHN   64
#define BQ    64            // query rows per CTA
#define BKT   128           // key rows per tile
#define NTILE 16
#define NELEM ((size_t)BHN * S_LEN * DH)   // 8388608

// smem: Q [64x64], K/V [128x64] bf16 hi/lo swizzled tiles
#define OFF_QH 0
#define OFF_QL 8192
#define OFF_KH 16384
#define OFF_KL 32768
#define OFF_VH 49152
#define OFF_VL 65536
#define SMEM_SZ 81920
// post-loop reuse
#define OFF_RS  OFF_QH
#define OFF_INV (OFF_QH + 512)
#define OFF_OSM OFF_KH

typedef unsigned long long ull;

// pre-split bf16 hi/lo copies of q,k,v (written by presplit kernel)
__device__ __align__(16) uint2 g_qhi[NELEM / 4], g_qlo[NELEM / 4];
__device__ __align__(16) uint2 g_khi[NELEM / 4], g_klo[NELEM / 4];
__device__ __align__(16) uint2 g_vhi[NELEM / 4], g_vlo[NELEM / 4];

// ---------------- helpers ----------------
__device__ __forceinline__ uint32_t s2u(const void* p) {
    uint32_t a;
    asm("{ .reg .u64 t; cvta.to.shared.u64 t, %1; cvt.u32.u64 %0, t; }" : "=r"(a) : "l"(p));
    return a;
}
__device__ __forceinline__ void ldsm4(uint32_t a, uint32_t* r) {
    asm volatile("ldmatrix.sync.aligned.m8n8.x4.shared.b16 {%0,%1,%2,%3}, [%4];"
                 : "=r"(r[0]), "=r"(r[1]), "=r"(r[2]), "=r"(r[3]) : "r"(a));
}
__device__ __forceinline__ void ldsm4t(uint32_t a, uint32_t* r) {
    asm volatile("ldmatrix.sync.aligned.m8n8.x4.trans.shared.b16 {%0,%1,%2,%3}, [%4];"
                 : "=r"(r[0]), "=r"(r[1]), "=r"(r[2]), "=r"(r[3]) : "r"(a));
}
__device__ __forceinline__ void mma_bf16(float* d, const uint32_t* a,
                                         uint32_t b0, uint32_t b1) {
    asm volatile("mma.sync.aligned.m16n8k16.row.col.f32.bf16.bf16.f32 "
                 "{%0,%1,%2,%3},{%4,%5,%6,%7},{%8,%9},{%0,%1,%2,%3};"
                 : "+f"(d[0]), "+f"(d[1]), "+f"(d[2]), "+f"(d[3])
                 : "r"(a[0]), "r"(a[1]), "r"(a[2]), "r"(a[3]), "r"(b0), "r"(b1));
}
__device__ __forceinline__ uint32_t pk2(float lo, float hi) {
    uint32_t r;
    asm("cvt.rn.bf16x2.f32 %0, %1, %2;" : "=r"(r) : "f"(hi), "f"(lo));
    return r;
}
__device__ __forceinline__ float lo16f(uint32_t u) { return __uint_as_float(u << 16); }
__device__ __forceinline__ float hi16f(uint32_t u) { return __uint_as_float(u & 0xFFFF0000u); }

__device__ __forceinline__ void cpa16(uint32_t dst, const void* src) {
    asm volatile("cp.async.cg.shared.global [%0], [%1], 16;" :: "r"(dst), "l"(src));
}
#define CPA_COMMIT() asm volatile("cp.async.commit_group;" ::: "memory")
#define CPA_WAIT0()  asm volatile("cp.async.wait_group 0;" ::: "memory")

// ---------------- pre-pass: fp32 -> bf16 hi/lo split ----------------
__global__ __launch_bounds__(256) void presplit(const float4* __restrict__ src,
                                                uint2* __restrict__ dhi,
                                                uint2* __restrict__ dlo)
{
    int i = blockIdx.x * blockDim.x + threadIdx.x;
    float4 t = src[i];
    uint32_t h01 = pk2(t.x, t.y), h23 = pk2(t.z, t.w);
    uint32_t l01 = pk2(t.x - lo16f(h01), t.y - hi16f(h01));
    uint32_t l23 = pk2(t.z - lo16f(h23), t.w - hi16f(h23));
    dhi[i] = make_uint2(h01, h23);
    dlo[i] = make_uint2(l01, l23);
}

__global__ __launch_bounds__(256, 2)
void attn_mma(const int* __restrict__ mask,
              float* __restrict__ out, float* __restrict__ p)
{
    extern __shared__ char sm[];
    const uint32_t sb = s2u(sm);
    const int tid = threadIdx.x;
    const int wid = tid >> 5, lane = tid & 31;
    const int rg = wid >> 1;                 // row group (16 rows)
    const int nhalf = wid & 1;               // s-column half
    const int bh = blockIdx.y;
    const int q0 = blockIdx.x * BQ;

    // cp.async thread mapping: chunk c = tid&7 (16B), row base = tid>>3
    const int cc = tid & 7, rr = tid >> 3;
    const uint32_t dcol = ((uint32_t)cc) << 4;

    // ---- prologue: Q tile via cp.async (rows 0..63)
    {
        const char* qh = (const char*)g_qhi + ((size_t)bh * S_LEN + q0) * 128;
        const char* ql = (const char*)g_qlo + ((size_t)bh * S_LEN + q0) * 128;
        #pragma unroll
        for (int ps = 0; ps < 2; ++ps) {
            int row = rr + ps * 32;
            uint32_t doff = (uint32_t)row * 128 + (dcol ^ (((uint32_t)row & 7) << 4));
            size_t soff = (size_t)row * 128 + cc * 16;
            cpa16(sb + OFF_QH + doff, qh + soff);
            cpa16(sb + OFF_QL + doff, ql + soff);
        }
        CPA_COMMIT();
    }

    float Oacc[8][4];
    #pragma unroll
    for (int i = 0; i < 8; ++i)
        #pragma unroll
        for (int c = 0; c < 4; ++c) Oacc[i][c] = 0.f;
    float esum0 = 0.f, esum1 = 0.f;

    // epilogue thread mapping (m16n8 accum layout)
    const int r0l = rg * 16 + (lane >> 2);
    const int coff = (lane & 3) * 2;

    // ldmatrix lane mappings (XOR applied AFTER column adds)
    const int arow = rg * 16 + (lane & 15);
    const uint32_t arowoff = (uint32_t)arow * 128;
    const uint32_t acol0 = ((uint32_t)(lane >> 4)) << 4;
    const uint32_t axor = ((uint32_t)arow & 7) << 4;
    const int nrow = ((lane >> 4) << 3) + (lane & 7);
    const uint32_t nbase = (uint32_t)(nhalf * 64 + nrow) * 128;
    const uint32_t ncol0 = (((uint32_t)lane >> 3) & 1) << 4;
    const uint32_t nxor = ((uint32_t)(nrow & 7)) << 4;
    const int vrow = (((lane >> 3) & 1) << 3) + (lane & 7);
    const uint32_t vbase_off = (uint32_t)(nhalf * 64 + vrow) * 128;
    const uint32_t vcol0 = ((uint32_t)(lane >> 4)) << 4;
    const uint32_t vxor = ((uint32_t)(vrow & 7)) << 4;

    const char* khb = (const char*)g_khi + (size_t)bh * S_LEN * 128;
    const char* klb = (const char*)g_klo + (size_t)bh * S_LEN * 128;
    const char* vhb = (const char*)g_vhi + (size_t)bh * S_LEN * 128;
    const char* vlb = (const char*)g_vlo + (size_t)bh * S_LEN * 128;

    for (int kb = 0; kb < NTILE; ++kb) {
        __syncthreads();                     // prev tile reads done
        // ---- K/V tiles via cp.async (128 rows x 4 arrays)
        {
            const size_t tb = (size_t)kb * BKT * 128;
            #pragma unroll
            for (int ps = 0; ps < 4; ++ps) {
                int row = rr + ps * 32;
                uint32_t doff = (uint32_t)row * 128 + (dcol ^ (((uint32_t)row & 7) << 4));
                size_t soff = tb + (size_t)row * 128 + cc * 16;
                cpa16(sb + OFF_KH + doff, khb + soff);
                cpa16(sb + OFF_KL + doff, klb + soff);
                cpa16(sb + OFF_VH + doff, vhb + soff);
                cpa16(sb + OFF_VL + doff, vlb + soff);
            }
            CPA_COMMIT();
            CPA_WAIT0();
        }
        __syncthreads();

        // ---- GEMM1: S[16 x 64] per warp = Q . K^T (3-term bf16 split)
        float acc[8][4];
        #pragma unroll
        for (int i = 0; i < 8; ++i)
            #pragma unroll
            for (int c = 0; c < 4; ++c) acc[i][c] = 0.f;

        #pragma unroll
        for (int ks = 0; ks < 4; ++ks) {
            uint32_t ah[4], al[4];
            const uint32_t ao = arowoff + ((acol0 + (uint32_t)ks * 32) ^ axor);
            ldsm4(sb + OFF_QH + ao, ah);
            ldsm4(sb + OFF_QL + ao, al);
            #pragma unroll
            for (int np = 0; np < 4; ++np) {
                uint32_t bh4[4], bl4[4];
                const uint32_t bo = nbase + (uint32_t)np * 2048 +
                                    ((ncol0 + (uint32_t)ks * 32) ^ nxor);
                ldsm4(sb + OFF_KH + bo, bh4);
                ldsm4(sb + OFF_KL + bo, bl4);
                mma_bf16(acc[np * 2], ah, bh4[0], bh4[1]);
                mma_bf16(acc[np * 2], ah, bl4[0], bl4[1]);
                mma_bf16(acc[np * 2], al, bh4[0], bh4[1]);
                mma_bf16(acc[np * 2 + 1], ah, bh4[2], bh4[3]);
                mma_bf16(acc[np * 2 + 1], ah, bl4[2], bl4[3]);
                mma_bf16(acc[np * 2 + 1], al, bh4[2], bh4[3]);
            }
        }

        // ---- epilogue: mask + __expf, unnormalized p write, E frags in regs
        uint32_t Eh[4][4], El[4][4];
        const int cb = kb * BKT + nhalf * 64 + coff;
        const int* mrow0 = mask + (size_t)(q0 + r0l) * S_LEN + cb;
        const int* mrow1 = mrow0 + 8 * S_LEN;
        float* prow0 = p + ((size_t)(bh * S_LEN) + q0 + r0l) * S_LEN + cb;
        float* prow1 = prow0 + (size_t)8 * S_LEN;
        #pragma unroll
        for (int nt = 0; nt < 8; ++nt) {
            const int2 m0 = *(const int2*)(mrow0 + nt * 8);
            const int2 m1 = *(const int2*)(mrow1 + nt * 8);
            float e0 = m0.x ? __expf(acc[nt][0] * 0.125f) : 0.f;
            float e1 = m0.y ? __expf(acc[nt][1] * 0.125f) : 0.f;
            float e2 = m1.x ? __expf(acc[nt][2] * 0.125f) : 0.f;
            float e3 = m1.y ? __expf(acc[nt][3] * 0.125f) : 0.f;
            *(float2*)(prow0 + nt * 8) = make_float2(e0, e1);
            *(float2*)(prow1 + nt * 8) = make_float2(e2, e3);
            esum0 += e0 + e1;
            esum1 += e2 + e3;
            uint32_t u01 = pk2(e0, e1), u23 = pk2(e2, e3);
            const int kk = nt >> 1, sl = (nt & 1) * 2;
            Eh[kk][sl + 0] = u01;
            Eh[kk][sl + 1] = u23;
            El[kk][sl + 0] = pk2(e0 - lo16f(u01), e1 - hi16f(u01));
            El[kk][sl + 1] = pk2(e2 - lo16f(u23), e3 - hi16f(u23));
        }

        // ---- GEMM2: O[16 x 64] += E(k-half) . V(k-half)  (3-term split)
        #pragma unroll
        for (int kk = 0; kk < 4; ++kk) {
            const uint32_t vrt = vbase_off + (uint32_t)kk * 2048;
            #pragma unroll
            for (int dt2 = 0; dt2 < 4; ++dt2) {
                uint32_t vh4[4], vl4[4];
                const uint32_t o = vrt + ((vcol0 + (uint32_t)dt2 * 32) ^ vxor);
                ldsm4t(sb + OFF_VH + o, vh4);
                ldsm4t(sb + OFF_VL + o, vl4);
                mma_bf16(Oacc[dt2 * 2], Eh[kk], vh4[0], vh4[1]);
                mma_bf16(Oacc[dt2 * 2], Eh[kk], vl4[0], vl4[1]);
                mma_bf16(Oacc[dt2 * 2], El[kk], vh4[0], vh4[1]);
                mma_bf16(Oacc[dt2 * 2 + 1], Eh[kk], vh4[2], vh4[3]);
                mma_bf16(Oacc[dt2 * 2 + 1], Eh[kk], vl4[2], vl4[3]);
                mma_bf16(Oacc[dt2 * 2 + 1], El[kk], vh4[2], vh4[3]);
            }
        }
    }
    __syncthreads();      // all tile reads done; smem reusable

    // ---- row sums: quad reduce, publish per-half, combine
    esum0 += __shfl_xor_sync(0xffffffffu, esum0, 1);
    esum0 += __shfl_xor_sync(0xffffffffu, esum0, 2);
    esum1 += __shfl_xor_sync(0xffffffffu, esum1, 1);
    esum1 += __shfl_xor_sync(0xffffffffu, esum1, 2);
    float* rsum = (float*)(sm + OFF_RS);
    float* inv_s = (float*)(sm + OFF_INV);
    if ((lane & 3) == 0) {
        rsum[nhalf * 64 + r0l] = esum0;
        rsum[nhalf * 64 + r0l + 8] = esum1;
    }
    float* Osm = (float*)(sm + OFF_OSM);
    if (nhalf == 1) {
        #pragma unroll
        for (int dt = 0; dt < 8; ++dt) {
            *(float2*)&Osm[r0l * 64 + dt * 8 + coff] = make_float2(Oacc[dt][0], Oacc[dt][1]);
            *(float2*)&Osm[(r0l + 8) * 64 + dt * 8 + coff] = make_float2(Oacc[dt][2], Oacc[dt][3]);
        }
    }
    __syncthreads();
    if (tid < 64) inv_s[tid] = 1.f / (rsum[tid] + rsum[64 + tid]);
    __syncthreads();

    if (nhalf == 0) {
        const float inv0 = inv_s[r0l], inv1 = inv_s[r0l + 8];
        float* orow0 = out + ((size_t)(bh * S_LEN) + q0 + r0l) * DH + coff;
        float* orow1 = orow0 + 8 * DH;
        #pragma unroll
        for (int dt = 0; dt < 8; ++dt) {
            float2 a0 = *(float2*)&Osm[r0l * 64 + dt * 8 + coff];
            float2 a1 = *(float2*)&Osm[(r0l + 8) * 64 + dt * 8 + coff];
            *(float2*)(orow0 + dt * 8) =
                make_float2((Oacc[dt][0] + a0.x) * inv0, (Oacc[dt][1] + a0.y) * inv0);
            *(float2*)(orow1 + dt * 8) =
                make_float2((Oacc[dt][2] + a1.x) * inv1, (Oacc[dt][3] + a1.y) * inv1);
        }
    }

    // ---- fused p normalization for this CTA's 64 rows
    float4* p4 = (float4*)(p + ((size_t)(bh * S_LEN) + q0) * S_LEN);
    #pragma unroll 4
    for (int i = tid; i < BQ * S_LEN / 4; i += 256) {
        float inv = inv_s[i >> 9];
        float4 t = p4[i];
        t.x *= inv; t.y *= inv; t.z *= inv; t.w *= inv;
        p4[i] = t;
    }
}

extern "C" void kernel_launch(void* const* d_in, const int* in_sizes, int n_in,
                              void* d_out, int out_size)
{
    const float* q    = (const float*)d_in[0];
    const float* k    = (const float*)d_in[1];
    const float* v    = (const float*)d_in[2];
    const int*   mask = (const int*)d_in[3];

    float* out = (float*)d_out;
    float* p   = out + NELEM;

    uint2 *qhi, *qlo, *khi, *klo, *vhi, *vlo;
    cudaGetSymbolAddress((void**)&qhi, g_qhi);
    cudaGetSymbolAddress((void**)&qlo, g_qlo);
    cudaGetSymbolAddress((void**)&khi, g_khi);
    cudaGetSymbolAddress((void**)&klo, g_klo);
    cudaGetSymbolAddress((void**)&vhi, g_vhi);
    cudaGetSymbolAddress((void**)&vlo, g_vlo);

    const unsigned gpre = (unsigned)(NELEM / 4 / 256);
    presplit<<<gpre, 256>>>((const float4*)q, qhi, qlo);
    presplit<<<gpre, 256>>>((const float4*)k, khi, klo);
    presplit<<<gpre, 256>>>((const float4*)v, vhi, vlo);

    cudaFuncSetAttribute(attn_mma, cudaFuncAttributeMaxDynamicSharedMemorySize, SMEM_SZ);
    dim3 g1(S_LEN / BQ, BHN);
    attn_mma<<<g1, 256, SMEM_SZ>>>(mask, out, p);
}

// round 9
// speedup vs baseline: 1.3261x; 1.0465x over previous
#include <cuda_runtime.h>
#include <cuda_bf16.h>
#include <cstdint>

// Problem constants: B=4, H=16, S=2048, D=64
#define S_LEN 2048
#define DH    64
#define BHN   64
#define BQ    64            // query rows per CTA
#define BKT   64            // key rows per tile
#define NTILE 32
#define NELEM ((size_t)BHN * S_LEN * DH)   // 8388608

// smem: Q hi/lo [64x64] + 3-stage ring of {KH,KL,VH,VL} [64x64] bf16 tiles
#define OFF_QH 0
#define OFF_QL 8192
#define OFF_ST 16384        // + slot*32768 ; within: KH 0, KL 8K, VH 16K, VL 24K
#define SMEM_SZ (16384 + 3 * 32768)   // 114688
// post-loop reuse
#define OFF_RS  0
#define OFF_INV 512
#define OFF_OSM 16384

typedef unsigned long long ull;

// pre-split bf16 hi/lo copies of q,k,v + bit-packed mask
__device__ __align__(16) uint2 g_qhi[NELEM / 4], g_qlo[NELEM / 4];
__device__ __align__(16) uint2 g_khi[NELEM / 4], g_klo[NELEM / 4];
__device__ __align__(16) uint2 g_vhi[NELEM / 4], g_vlo[NELEM / 4];
__device__ uint32_t g_mbits[(size_t)S_LEN * (S_LEN / 32)];   // [row][word]

// ---------------- helpers ----------------
__device__ __forceinline__ uint32_t s2u(const void* p) {
    uint32_t a;
    asm("{ .reg .u64 t; cvta.to.shared.u64 t, %1; cvt.u32.u64 %0, t; }" : "=r"(a) : "l"(p));
    return a;
}
__device__ __forceinline__ void ldsm4(uint32_t a, uint32_t* r) {
    asm volatile("ldmatrix.sync.aligned.m8n8.x4.shared.b16 {%0,%1,%2,%3}, [%4];"
                 : "=r"(r[0]), "=r"(r[1]), "=r"(r[2]), "=r"(r[3]) : "r"(a));
}
__device__ __forceinline__ void ldsm4t(uint32_t a, uint32_t* r) {
    asm volatile("ldmatrix.sync.aligned.m8n8.x4.trans.shared.b16 {%0,%1,%2,%3}, [%4];"
                 : "=r"(r[0]), "=r"(r[1]), "=r"(r[2]), "=r"(r[3]) : "r"(a));
}
__device__ __forceinline__ void mma_bf16(float* d, const uint32_t* a,
                                         uint32_t b0, uint32_t b1) {
    asm volatile("mma.sync.aligned.m16n8k16.row.col.f32.bf16.bf16.f32 "
                 "{%0,%1,%2,%3},{%4,%5,%6,%7},{%8,%9},{%0,%1,%2,%3};"
                 : "+f"(d[0]), "+f"(d[1]), "+f"(d[2]), "+f"(d[3])
                 : "r"(a[0]), "r"(a[1]), "r"(a[2]), "r"(a[3]), "r"(b0), "r"(b1));
}
__device__ __forceinline__ uint32_t pk2(float lo, float hi) {
    uint32_t r;
    asm("cvt.rn.bf16x2.f32 %0, %1, %2;" : "=r"(r) : "f"(hi), "f"(lo));
    return r;
}
__device__ __forceinline__ float lo16f(uint32_t u) { return __uint_as_float(u << 16); }
__device__ __forceinline__ float hi16f(uint32_t u) { return __uint_as_float(u & 0xFFFF0000u); }

__device__ __forceinline__ void cpa16(uint32_t dst, const void* src) {
    asm volatile("cp.async.cg.shared.global [%0], [%1], 16;" :: "r"(dst), "l"(src));
}
#define CPA_COMMIT() asm volatile("cp.async.commit_group;" ::: "memory")
#define CPA_WAIT1()  asm volatile("cp.async.wait_group 1;" ::: "memory")

// ---------------- pre-pass kernels ----------------
__global__ __launch_bounds__(256) void presplit(const float4* __restrict__ src,
                                                uint2* __restrict__ dhi,
                                                uint2* __restrict__ dlo)
{
    int i = blockIdx.x * blockDim.x + threadIdx.x;
    float4 t = src[i];
    uint32_t h01 = pk2(t.x, t.y), h23 = pk2(t.z, t.w);
    uint32_t l01 = pk2(t.x - lo16f(h01), t.y - hi16f(h01));
    uint32_t l23 = pk2(t.z - lo16f(h23), t.w - hi16f(h23));
    dhi[i] = make_uint2(h01, h23);
    dlo[i] = make_uint2(l01, l23);
}

__global__ __launch_bounds__(256) void pmask(const int* __restrict__ mask,
                                             uint32_t* __restrict__ bits)
{
    int idx = blockIdx.x * blockDim.x + threadIdx.x;   // word index
    const int4* m4 = (const int4*)mask + (size_t)idx * 8;
    uint32_t b = 0;
    #pragma unroll
    for (int i = 0; i < 8; ++i) {
        int4 v = m4[i];
        b |= (v.x != 0 ? 1u : 0u) << (i * 4);
        b |= (v.y != 0 ? 1u : 0u) << (i * 4 + 1);
        b |= (v.z != 0 ? 1u : 0u) << (i * 4 + 2);
        b |= (v.w != 0 ? 1u : 0u) << (i * 4 + 3);
    }
    bits[idx] = b;
}

__global__ __launch_bounds__(256, 2)
void attn_mma(float* __restrict__ out, float* __restrict__ p)
{
    extern __shared__ char sm[];
    const uint32_t sb = s2u(sm);
    const int tid = threadIdx.x;
    const int wid = tid >> 5, lane = tid & 31;
    const int rg = wid >> 1;                 // row group (16 rows)
    const int nhalf = wid & 1;               // 32-col half of tile
    const int bh = blockIdx.y;
    const int q0 = blockIdx.x * BQ;

    // cp.async mapping: chunk cc (16B), rows rr, rr+32
    const int cc = tid & 7, rr = tid >> 3;
    const uint32_t dcol = ((uint32_t)cc) << 4;
    const uint32_t drow0 = (uint32_t)rr * 128 + (dcol ^ (((uint32_t)rr & 7) << 4));
    const uint32_t drow1 = (uint32_t)(rr + 32) * 128 + (dcol ^ ((((uint32_t)rr + 32) & 7) << 4));
    const size_t srow0 = (size_t)rr * 128 + cc * 16;
    const size_t srow1 = (size_t)(rr + 32) * 128 + cc * 16;

    const char* khb = (const char*)g_khi + (size_t)bh * S_LEN * 128;
    const char* klb = (const char*)g_klo + (size_t)bh * S_LEN * 128;
    const char* vhb = (const char*)g_vhi + (size_t)bh * S_LEN * 128;
    const char* vlb = (const char*)g_vlo + (size_t)bh * S_LEN * 128;

    // ---- prologue: Q + stage0 (group 0), stage1 (group 1)
    {
        const char* qh = (const char*)g_qhi + ((size_t)bh * S_LEN + q0) * 128;
        const char* ql = (const char*)g_qlo + ((size_t)bh * S_LEN + q0) * 128;
        cpa16(sb + OFF_QH + drow0, qh + srow0);
        cpa16(sb + OFF_QH + drow1, qh + srow1);
        cpa16(sb + OFF_QL + drow0, ql + srow0);
        cpa16(sb + OFF_QL + drow1, ql + srow1);
        const uint32_t st = sb + OFF_ST;
        cpa16(st + drow0, khb + srow0);          cpa16(st + drow1, khb + srow1);
        cpa16(st + 8192 + drow0, klb + srow0);   cpa16(st + 8192 + drow1, klb + srow1);
        cpa16(st + 16384 + drow0, vhb + srow0);  cpa16(st + 16384 + drow1, vhb + srow1);
        cpa16(st + 24576 + drow0, vlb + srow0);  cpa16(st + 24576 + drow1, vlb + srow1);
        CPA_COMMIT();
        const uint32_t s1 = sb + OFF_ST + 32768;
        const size_t tb = 8192;
        cpa16(s1 + drow0, khb + tb + srow0);          cpa16(s1 + drow1, khb + tb + srow1);
        cpa16(s1 + 8192 + drow0, klb + tb + srow0);   cpa16(s1 + 8192 + drow1, klb + tb + srow1);
        cpa16(s1 + 16384 + drow0, vhb + tb + srow0);  cpa16(s1 + 16384 + drow1, vhb + tb + srow1);
        cpa16(s1 + 24576 + drow0, vlb + tb + srow0);  cpa16(s1 + 24576 + drow1, vlb + tb + srow1);
        CPA_COMMIT();
    }

    float Oacc[8][4];
    #pragma unroll
    for (int i = 0; i < 8; ++i)
        #pragma unroll
        for (int c = 0; c < 4; ++c) Oacc[i][c] = 0.f;
    float esum0 = 0.f, esum1 = 0.f;

    // epilogue thread mapping (m16n8 accum layout)
    const int r0l = rg * 16 + (lane >> 2);
    const int coff = (lane & 3) * 2;

    // ldmatrix lane mappings (XOR applied AFTER column adds)
    const int arow = rg * 16 + (lane & 15);
    const uint32_t arowoff = (uint32_t)arow * 128;
    const uint32_t acol0 = ((uint32_t)(lane >> 4)) << 4;
    const uint32_t axor = ((uint32_t)arow & 7) << 4;
    const int nrow = ((lane >> 4) << 3) + (lane & 7);
    const uint32_t nbase = (uint32_t)(nhalf * 32 + nrow) * 128;
    const uint32_t ncol0 = (((uint32_t)lane >> 3) & 1) << 4;
    const uint32_t nxor = ((uint32_t)(nrow & 7)) << 4;
    const int vrow = (((lane >> 3) & 1) << 3) + (lane & 7);
    const uint32_t vbase_off = (uint32_t)(nhalf * 32 + vrow) * 128;
    const uint32_t vcol0 = ((uint32_t)(lane >> 4)) << 4;
    const uint32_t vxor = ((uint32_t)(vrow & 7)) << 4;

    const uint32_t* mb0 = g_mbits + (size_t)(q0 + r0l) * 64 + nhalf;
    const uint32_t* mb1 = mb0 + 8 * 64;

    for (int kb = 0; kb < NTILE; ++kb) {
        CPA_WAIT1();                         // stage kb complete (kb+1 may pend)
        __syncthreads();
        const uint32_t st = sb + OFF_ST + (uint32_t)(kb % 3) * 32768;

        // mask words for this tile (L2-hot; used in epilogue)
        const uint32_t w0 = mb0[kb * 2];
        const uint32_t w1 = mb1[kb * 2];

        // ---- GEMM1: S[16 x 32] per warp = Q . K^T (3-term bf16 split)
        float acc[4][4];
        #pragma unroll
        for (int i = 0; i < 4; ++i)
            #pragma unroll
            for (int c = 0; c < 4; ++c) acc[i][c] = 0.f;

        #pragma unroll
        for (int ks = 0; ks < 4; ++ks) {
            uint32_t ah[4], al[4];
            const uint32_t ao = arowoff + ((acol0 + (uint32_t)ks * 32) ^ axor);
            ldsm4(sb + OFF_QH + ao, ah);
            ldsm4(sb + OFF_QL + ao, al);
            #pragma unroll
            for (int np = 0; np < 2; ++np) {
                uint32_t bh4[4], bl4[4];
                const uint32_t bo = nbase + (uint32_t)np * 2048 +
                                    ((ncol0 + (uint32_t)ks * 32) ^ nxor);
                ldsm4(st + bo, bh4);
                ldsm4(st + 8192 + bo, bl4);
                mma_bf16(acc[np * 2], ah, bh4[0], bh4[1]);
                mma_bf16(acc[np * 2], ah, bl4[0], bl4[1]);
                mma_bf16(acc[np * 2], al, bh4[0], bh4[1]);
                mma_bf16(acc[np * 2 + 1], ah, bh4[2], bh4[3]);
                mma_bf16(acc[np * 2 + 1], ah, bl4[2], bl4[3]);
                mma_bf16(acc[np * 2 + 1], al, bh4[2], bh4[3]);
            }
        }

        // ---- epilogue: bit-mask + __expf, unnormalized p write, E frags
        uint32_t Eh[2][4], El[2][4];
        const int cb = kb * BKT + nhalf * 32 + coff;
        float* prow0 = p + ((size_t)(bh * S_LEN) + q0 + r0l) * S_LEN + cb;
        float* prow1 = prow0 + (size_t)8 * S_LEN;
        #pragma unroll
        for (int nt = 0; nt < 4; ++nt) {
            const int sh = coff + nt * 8;
            float e0 = (w0 >> sh) & 1 ? __expf(acc[nt][0] * 0.125f) : 0.f;
            float e1 = (w0 >> (sh + 1)) & 1 ? __expf(acc[nt][1] * 0.125f) : 0.f;
            float e2 = (w1 >> sh) & 1 ? __expf(acc[nt][2] * 0.125f) : 0.f;
            float e3 = (w1 >> (sh + 1)) & 1 ? __expf(acc[nt][3] * 0.125f) : 0.f;
            *(float2*)(prow0 + nt * 8) = make_float2(e0, e1);
            *(float2*)(prow1 + nt * 8) = make_float2(e2, e3);
            esum0 += e0 + e1;
            esum1 += e2 + e3;
            uint32_t u01 = pk2(e0, e1), u23 = pk2(e2, e3);
            const int kk = nt >> 1, sl = (nt & 1) * 2;
            Eh[kk][sl + 0] = u01;
            Eh[kk][sl + 1] = u23;
            El[kk][sl + 0] = pk2(e0 - lo16f(u01), e1 - hi16f(u01));
            El[kk][sl + 1] = pk2(e2 - lo16f(u23), e3 - hi16f(u23));
        }

        // ---- GEMM2: O[16 x 64] += E(k-slice) . V(k-slice)  (3-term split)
        #pragma unroll
        for (int kk = 0; kk < 2; ++kk) {
            const uint32_t vrt = vbase_off + (uint32_t)kk * 2048;
            #pragma unroll
            for (int dt2 = 0; dt2 < 4; ++dt2) {
                uint32_t vh4[4], vl4[4];
                const uint32_t o = vrt + ((vcol0 + (uint32_t)dt2 * 32) ^ vxor);
                ldsm4t(st + 16384 + o, vh4);
                ldsm4t(st + 24576 + o, vl4);
                mma_bf16(Oacc[dt2 * 2], Eh[kk], vh4[0], vh4[1]);
                mma_bf16(Oacc[dt2 * 2], Eh[kk], vl4[0], vl4[1]);
                mma_bf16(Oacc[dt2 * 2], El[kk], vh4[0], vh4[1]);
                mma_bf16(Oacc[dt2 * 2 + 1], Eh[kk], vh4[2], vh4[3]);
                mma_bf16(Oacc[dt2 * 2 + 1], Eh[kk], vl4[2], vl4[3]);
                mma_bf16(Oacc[dt2 * 2 + 1], El[kk], vh4[2], vh4[3]);
            }
        }

        // ---- issue stage kb+2 (slot is free: read finished at iter kb-1)
        if (kb + 2 < NTILE) {
            const uint32_t sn = sb + OFF_ST + (uint32_t)((kb + 2) % 3) * 32768;
            const size_t tb = (size_t)(kb + 2) * BKT * 128;
            cpa16(sn + drow0, khb + tb + srow0);          cpa16(sn + drow1, khb + tb + srow1);
            cpa16(sn + 8192 + drow0, klb + tb + srow0);   cpa16(sn + 8192 + drow1, klb + tb + srow1);
            cpa16(sn + 16384 + drow0, vhb + tb + srow0);  cpa16(sn + 16384 + drow1, vhb + tb + srow1);
            cpa16(sn + 24576 + drow0, vlb + tb + srow0);  cpa16(sn + 24576 + drow1, vlb + tb + srow1);
        }
        CPA_COMMIT();                        // unconditional: keeps group count aligned
    }
    __syncthreads();      // all tile reads done; smem reusable

    // ---- row sums: quad reduce, publish per-half, combine
    esum0 += __shfl_xor_sync(0xffffffffu, esum0, 1);
    esum0 += __shfl_xor_sync(0xffffffffu, esum0, 2);
    esum1 += __shfl_xor_sync(0xffffffffu, esum1, 1);
    esum1 += __shfl_xor_sync(0xffffffffu, esum1, 2);
    float* rsum = (float*)(sm + OFF_RS);
    float* inv_s = (float*)(sm + OFF_INV);
    if ((lane & 3) == 0) {
        rsum[nhalf * 64 + r0l] = esum0;
        rsum[nhalf * 64 + r0l + 8] = esum1;
    }
    float* Osm = (float*)(sm + OFF_OSM);
    if (nhalf == 1) {
        #pragma unroll
        for (int dt = 0; dt < 8; ++dt) {
            *(float2*)&Osm[r0l * 64 + dt * 8 + coff] = make_float2(Oacc[dt][0], Oacc[dt][1]);
            *(float2*)&Osm[(r0l + 8) * 64 + dt * 8 + coff] = make_float2(Oacc[dt][2], Oacc[dt][3]);
        }
    }
    __syncthreads();
    if (tid < 64) inv_s[tid] = 1.f / (rsum[tid] + rsum[64 + tid]);
    __syncthreads();

    if (nhalf == 0) {
        const float inv0 = inv_s[r0l], inv1 = inv_s[r0l + 8];
        float* orow0 = out + ((size_t)(bh * S_LEN) + q0 + r0l) * DH + coff;
        float* orow1 = orow0 + 8 * DH;
        #pragma unroll
        for (int dt = 0; dt < 8; ++dt) {
            float2 a0 = *(float2*)&Osm[r0l * 64 + dt * 8 + coff];
            float2 a1 = *(float2*)&Osm[(r0l + 8) * 64 + dt * 8 + coff];
            *(float2*)(orow0 + dt * 8) =
                make_float2((Oacc[dt][0] + a0.x) * inv0, (Oacc[dt][1] + a0.y) * inv0);
            *(float2*)(orow1 + dt * 8) =
                make_float2((Oacc[dt][2] + a1.x) * inv1, (Oacc[dt][3] + a1.y) * inv1);
        }
    }

    // ---- fused p normalization for this CTA's 64 rows
    float4* p4 = (float4*)(p + ((size_t)(bh * S_LEN) + q0) * S_LEN);
    #pragma unroll 4
    for (int i = tid; i < BQ * S_LEN / 4; i += 256) {
        float inv = inv_s[i >> 9];
        float4 t = p4[i];
        t.x *= inv; t.y *= inv; t.z *= inv; t.w *= inv;
        p4[i] = t;
    }
}

extern "C" void kernel_launch(void* const* d_in, const int* in_sizes, int n_in,
                              void* d_out, int out_size)
{
    const float* q    = (const float*)d_in[0];
    const float* k    = (const float*)d_in[1];
    const float* v    = (const float*)d_in[2];
    const int*   mask = (const int*)d_in[3];

    float* out = (float*)d_out;
    float* p   = out + NELEM;

    uint2 *qhi, *qlo, *khi, *klo, *vhi, *vlo;
    uint32_t* mbits;
    cudaGetSymbolAddress((void**)&qhi, g_qhi);
    cudaGetSymbolAddress((void**)&qlo, g_qlo);
    cudaGetSymbolAddress((void**)&khi, g_khi);
    cudaGetSymbolAddress((void**)&klo, g_klo);
    cudaGetSymbolAddress((void**)&vhi, g_vhi);
    cudaGetSymbolAddress((void**)&vlo, g_vlo);
    cudaGetSymbolAddress((void**)&mbits, g_mbits);

    const unsigned gpre = (unsigned)(NELEM / 4 / 256);
    presplit<<<gpre, 256>>>((const float4*)q, qhi, qlo);
    presplit<<<gpre, 256>>>((const float4*)k, khi, klo);
    presplit<<<gpre, 256>>>((const float4*)v, vhi, vlo);
    pmask<<<(unsigned)((size_t)S_LEN * (S_LEN / 32) / 256), 256>>>(mask, mbits);

    cudaFuncSetAttribute(attn_mma, cudaFuncAttributeMaxDynamicSharedMemorySize, SMEM_SZ);
    dim3 g1(S_LEN / BQ, BHN);
    attn_mma<<<g1, 256, SMEM_SZ>>>(out, p);
}